// round 10
// baseline (speedup 1.0000x reference)
#include <cuda_runtime.h>
#include <cuda_bf16.h>
#include <cuda_fp16.h>
#include <math_constants.h>
#include <cstdint>

#define NB 32
#define NC 256
#define HW 1024
#define NRP 16          // row-partial slices
#define NCP 32          // col-partial slices

static __device__ __constant__ float c_invT = 14.2857142857142857f; // 1/0.07

// Fragment-ordered operands:
// MhiP: tf32 hi, GEMM-A (feature_B): [b][it16 64][kt8 32][lane 32][4] f32
// NhiP: tf32 hi, GEMM-B (feature_A*invT): [b][jt8 128][kt8 32][lane 32][2] f32
// MbfP: bf16x2 cross A' = [hi(vkt<16) | lo(vkt>=16)]
// NbfP: bf16x2 cross B' = [lo(vkt<16) | hi(vkt>=16)]
__device__ float    g_MhiP[(size_t)NB * 64 * 32 * 128];
__device__ float    g_NhiP[(size_t)NB * 128 * 32 * 64];
__device__ uint32_t g_MbfP[(size_t)NB * 64 * 32 * 128];
__device__ uint32_t g_NbfP[(size_t)NB * 128 * 32 * 64];
__device__ __half   g_E[(size_t)NB * HW * HW];   // exp(2L - rm_slice - cm_slice)
__device__ float g_rmax[NB * HW];
__device__ float g_rinv[NB * HW];
__device__ float g_cmax[NB * HW];
__device__ float g_cinv[NB * HW];
__device__ float g_prm[(size_t)NRP * NB * HW];
__device__ float g_prs[(size_t)NRP * NB * HW];
__device__ float g_pcm[(size_t)NCP * NB * HW];
__device__ float g_pcs[(size_t)NCP * NB * HW];

// ---- helpers --------------------------------------------------------------
__device__ __forceinline__ float tf32_rna(float x) {
    uint32_t r;
    asm("cvt.rna.tf32.f32 %0, %1;" : "=r"(r) : "f"(x));
    return __uint_as_float(r);
}
__device__ __forceinline__ uint32_t bf2pack(float x, float y) {
    uint16_t lx = __bfloat16_as_ushort(__float2bfloat16(x));
    uint16_t ly = __bfloat16_as_ushort(__float2bfloat16(y));
    return ((uint32_t)ly << 16) | (uint32_t)lx;
}
__device__ __forceinline__ uint32_t smem_u32(const void* p) {
    uint32_t a;
    asm("{ .reg .u64 t; cvta.to.shared.u64 t, %1; cvt.u32.u64 %0, t; }"
        : "=r"(a) : "l"(p));
    return a;
}
__device__ __forceinline__ void cp16(uint32_t sdst, const void* gsrc) {
    asm volatile("cp.async.cg.shared.global [%0], [%1], 16;"
                 :: "r"(sdst), "l"(gsrc) : "memory");
}
__device__ __forceinline__ void cp_commit() {
    asm volatile("cp.async.commit_group;" ::: "memory");
}
template <int N>
__device__ __forceinline__ void cp_wait() {
    asm volatile("cp.async.wait_group %0;" :: "n"(N) : "memory");
}
__device__ __forceinline__ void mma_tf32(float c[4], const uint32_t a[4],
                                         const uint32_t b[2]) {
    asm volatile(
        "mma.sync.aligned.m16n8k8.row.col.f32.tf32.tf32.f32 "
        "{%0,%1,%2,%3}, {%4,%5,%6,%7}, {%8,%9}, {%0,%1,%2,%3};"
        : "+f"(c[0]), "+f"(c[1]), "+f"(c[2]), "+f"(c[3])
        : "r"(a[0]), "r"(a[1]), "r"(a[2]), "r"(a[3]), "r"(b[0]), "r"(b[1]));
}
__device__ __forceinline__ void mma_bf16(float c[4], const uint32_t a[4],
                                         const uint32_t b[2]) {
    asm volatile(
        "mma.sync.aligned.m16n8k16.row.col.f32.bf16.bf16.f32 "
        "{%0,%1,%2,%3}, {%4,%5,%6,%7}, {%8,%9}, {%0,%1,%2,%3};"
        : "+f"(c[0]), "+f"(c[1]), "+f"(c[2]), "+f"(c[3])
        : "r"(a[0]), "r"(a[1]), "r"(a[2]), "r"(a[3]), "r"(b[0]), "r"(b[1]));
}

// ---------------------------------------------------------------------------
// Kernel 1: split + repack (tf32 hi frags + bf16 cross frags).
// ---------------------------------------------------------------------------
__global__ void split_frag_kernel(const float* __restrict__ A,
                                  const float* __restrict__ Bf) {
    __shared__ float s[32][33];
    int zb   = blockIdx.z;
    int side = zb >> 5;
    int b    = zb & 31;
    int c0   = blockIdx.y * 32;
    int hw0  = blockIdx.x * 32;
    const float* src = (side ? A : Bf) + (size_t)b * NC * HW;
    int t    = threadIdx.x;
    int lane = t & 31;
    int g    = lane >> 2;
    int tig  = lane & 3;
    int blk  = t >> 5;
    {
#pragma unroll
        for (int r = 0; r < 4; r++) {
            int cr = blk + r * 8;
            s[cr][lane] = src[(size_t)(c0 + cr) * HW + hw0 + lane];
        }
    }
    __syncthreads();

    if (side == 0) {
        {
            int it_l = blk >> 2, kt8_l = blk & 3;
            float hi[4];
#pragma unroll
            for (int r = 0; r < 4; r++) {
                int row = it_l * 16 + g + 8 * (r & 1);
                int k   = kt8_l * 8 + tig + 4 * (r >> 1);
                hi[r] = tf32_rna(s[k][row]);
            }
            int it_g = (hw0 >> 4) + it_l;
            int kt_g = (c0 >> 3) + kt8_l;
            size_t o = (((size_t)b * 64 + it_g) * 32 + kt_g) * 128 + lane * 4;
            *(float4*)(g_MhiP + o) = make_float4(hi[0], hi[1], hi[2], hi[3]);
        }
        {
            int u = blk >> 1, h = blk & 1;
            int it_l = u >> 1, kt16_l = u & 1;
            uint32_t pk[4];
#pragma unroll
            for (int r = 0; r < 4; r++) {
                int row = it_l * 16 + g + 8 * (r & 1);
                int kb  = kt16_l * 16 + 2 * tig + 8 * (r >> 1);
                float v0 = s[kb][row], v1 = s[kb + 1][row];
                float h0 = tf32_rna(v0), h1 = tf32_rna(v1);
                pk[r] = h ? bf2pack(v0 - h0, v1 - h1) : bf2pack(h0, h1);
            }
            int it_g = (hw0 >> 4) + it_l;
            int vkt  = (h ? 16 : 0) + (c0 >> 4) + kt16_l;
            size_t o = (((size_t)b * 64 + it_g) * 32 + vkt) * 128 + lane * 4;
            *(uint4*)(g_MbfP + o) = make_uint4(pk[0], pk[1], pk[2], pk[3]);
        }
    } else {
#pragma unroll
        for (int h = 0; h < 2; h++) {
            int u = blk + h * 8;
            int jt_l = u & 3, kt8_l = u >> 2;
            float hi[2];
#pragma unroll
            for (int r = 0; r < 2; r++) {
                int row = jt_l * 8 + g;
                int k   = kt8_l * 8 + tig + 4 * r;
                hi[r] = tf32_rna(s[k][row] * c_invT);
            }
            int jt_g = (hw0 >> 3) + jt_l;
            int kt_g = (c0 >> 3) + kt8_l;
            size_t o = (((size_t)b * 128 + jt_g) * 32 + kt_g) * 64 + lane * 2;
            *(float2*)(g_NhiP + o) = make_float2(hi[0], hi[1]);
        }
        {
            int jt_l = blk & 3, kt16_l = blk >> 2;
            uint32_t ph[2], pl[2];
#pragma unroll
            for (int r = 0; r < 2; r++) {
                int row = jt_l * 8 + g;
                int kb  = kt16_l * 16 + 2 * tig + 8 * r;
                float v0 = s[kb][row] * c_invT, v1 = s[kb + 1][row] * c_invT;
                float h0 = tf32_rna(v0), h1 = tf32_rna(v1);
                ph[r] = bf2pack(h0, h1);
                pl[r] = bf2pack(v0 - h0, v1 - h1);
            }
            int jt_g = (hw0 >> 3) + jt_l;
            int ckt  = (c0 >> 4) + kt16_l;
            size_t base = ((size_t)b * 128 + jt_g) * 32;
            *(uint2*)(g_NbfP + (base + ckt) * 64 + lane * 2)      = make_uint2(pl[0], pl[1]);
            *(uint2*)(g_NbfP + (base + 16 + ckt) * 64 + lane * 2) = make_uint2(ph[0], ph[1]);
        }
    }
}

// ---------------------------------------------------------------------------
// Kernel 2: mixed tf32+bf16 GEMM, 3-stage pipeline, fused stats + fp16 E out.
// Stage (words): [0,2048) Ahi | [2048,4096) Bhi | [4096,6144) Abf | [6144,8192) Bbf
// ---------------------------------------------------------------------------
#define STG_W 8192
#define STG_B (STG_W * 4)
#define GEMM_SMEM (3 * STG_B)   // 98304 bytes

__device__ __forceinline__ void copy_chunk(uint32_t sbase, int ck,
                                           const float* MhiB, const uint32_t* MbfB,
                                           const float* NhiB, const uint32_t* NbfB,
                                           int t) {
#pragma unroll
    for (int q = 0; q < 2; q++) {   // Ahi
        int f4 = t + q * 256;
        int it = f4 >> 6, rem = f4 & 63;
        cp16(sbase + (uint32_t)f4 * 16, MhiB + (size_t)it * 4096 + ck * 256 + rem * 4);
    }
#pragma unroll
    for (int q = 0; q < 2; q++) {   // Bhi
        int f4 = t + q * 256;
        int jt = f4 >> 5, rem = f4 & 31;
        cp16(sbase + 8192 + (uint32_t)f4 * 16, NhiB + (size_t)jt * 2048 + ck * 128 + rem * 4);
    }
#pragma unroll
    for (int q = 0; q < 2; q++) {   // Abf
        int f4 = t + q * 256;
        int it = f4 >> 6, half = (f4 >> 5) & 1, rem = f4 & 31;
        cp16(sbase + 16384 + (uint32_t)f4 * 16,
             MbfB + (size_t)it * 4096 + (ck + half * 16) * 128 + rem * 4);
    }
#pragma unroll
    for (int q = 0; q < 2; q++) {   // Bbf
        int f4 = t + q * 256;
        int jt = f4 >> 5, half = (f4 >> 4) & 1, rem = f4 & 15;
        cp16(sbase + 24576 + (uint32_t)f4 * 16,
             NbfB + (size_t)jt * 2048 + (ck + half * 16) * 64 + rem * 4);
    }
    cp_commit();
}

__global__ void __launch_bounds__(256, 2) gemm_hmma_kernel() {
    extern __shared__ float sm[];
    uint32_t sbase = smem_u32(sm);
    int b   = blockIdx.z;
    int jt0 = blockIdx.x * 16;     // j0 = bx*128
    int it0 = blockIdx.y * 8;      // i0 = by*128
    int t    = threadIdx.x;
    int wid  = t >> 5;
    int lane = t & 31;
    int wm   = wid >> 1;
    int wn   = wid & 1;
    int g    = lane >> 2;
    int tig  = lane & 3;

    const float*    MhiB = g_MhiP + ((size_t)b * 64 + it0) * 4096;
    const uint32_t* MbfB = g_MbfP + ((size_t)b * 64 + it0) * 4096;
    const float*    NhiB = g_NhiP + ((size_t)b * 128 + jt0) * 2048;
    const uint32_t* NbfB = g_NbfP + ((size_t)b * 128 + jt0) * 2048;

    float acc[2][8][4];
#pragma unroll
    for (int m = 0; m < 2; m++)
#pragma unroll
        for (int n = 0; n < 8; n++)
#pragma unroll
            for (int r = 0; r < 4; r++) acc[m][n][r] = 0.0f;

    copy_chunk(sbase + 0 * STG_B, 0, MhiB, MbfB, NhiB, NbfB, t);
    copy_chunk(sbase + 1 * STG_B, 1, MhiB, MbfB, NhiB, NbfB, t);

    for (int c = 0; c < 16; c++) {
        if (c < 15) cp_wait<1>(); else cp_wait<0>();
        __syncthreads();
        if (c + 2 < 16)
            copy_chunk(sbase + ((c + 2) % 3) * STG_B, c + 2,
                       MhiB, MbfB, NhiB, NbfB, t);

        const float* sA = sm + (c % 3) * STG_W;
        const uint32_t* sAu = (const uint32_t*)sA;
        // tf32 hi terms
#pragma unroll
        for (int k8 = 0; k8 < 2; k8++) {
            uint32_t a[2][4];
#pragma unroll
            for (int m = 0; m < 2; m++) {
                float4 v = *(const float4*)(sA + (wm * 2 + m) * 256 + k8 * 128 + lane * 4);
                a[m][0] = __float_as_uint(v.x); a[m][1] = __float_as_uint(v.y);
                a[m][2] = __float_as_uint(v.z); a[m][3] = __float_as_uint(v.w);
            }
            uint32_t bf[8][2];
#pragma unroll
            for (int n = 0; n < 8; n++) {
                float2 v = *(const float2*)(sA + 2048 + (wn * 8 + n) * 128 + k8 * 64 + lane * 2);
                bf[n][0] = __float_as_uint(v.x); bf[n][1] = __float_as_uint(v.y);
            }
#pragma unroll
            for (int m = 0; m < 2; m++)
#pragma unroll
                for (int n = 0; n < 8; n++)
                    mma_tf32(acc[m][n], a[m], bf[n]);
        }
        // bf16 cross terms
#pragma unroll
        for (int half = 0; half < 2; half++) {
            uint32_t a[2][4];
#pragma unroll
            for (int m = 0; m < 2; m++) {
                uint4 v = *(const uint4*)(sAu + 4096 + (wm * 2 + m) * 256 + half * 128 + lane * 4);
                a[m][0] = v.x; a[m][1] = v.y; a[m][2] = v.z; a[m][3] = v.w;
            }
            uint32_t bf[8][2];
#pragma unroll
            for (int n = 0; n < 8; n++) {
                uint2 v = *(const uint2*)(sAu + 6144 + (wn * 8 + n) * 128 + half * 64 + lane * 2);
                bf[n][0] = v.x; bf[n][1] = v.y;
            }
#pragma unroll
            for (int m = 0; m < 2; m++)
#pragma unroll
                for (int n = 0; n < 8; n++)
                    mma_bf16(acc[m][n], a[m], bf[n]);
        }
    }

    int j0 = jt0 * 8;
    int i0 = it0 * 16;
    float rmP[2][2], cmP[8][2];

    // ---- fused row partials (save slice maxima) ----
    int rslice = blockIdx.x * 2 + wn;
#pragma unroll
    for (int m = 0; m < 2; m++)
#pragma unroll
        for (int rp = 0; rp < 2; rp++) {
            float rm = -CUDART_INF_F;
#pragma unroll
            for (int n = 0; n < 8; n++)
                rm = fmaxf(rm, fmaxf(acc[m][n][rp * 2], acc[m][n][rp * 2 + 1]));
            rm = fmaxf(rm, __shfl_xor_sync(0xFFFFFFFFu, rm, 1));
            rm = fmaxf(rm, __shfl_xor_sync(0xFFFFFFFFu, rm, 2));
            float rs = 0.0f;
#pragma unroll
            for (int n = 0; n < 8; n++)
                rs += __expf(acc[m][n][rp * 2] - rm) +
                      __expf(acc[m][n][rp * 2 + 1] - rm);
            rs += __shfl_xor_sync(0xFFFFFFFFu, rs, 1);
            rs += __shfl_xor_sync(0xFFFFFFFFu, rs, 2);
            rmP[m][rp] = rm;
            if (tig == 0) {
                int i = i0 + wm * 32 + m * 16 + rp * 8 + g;
                size_t idx = (size_t)rslice * NB * HW + b * HW + i;
                g_prm[idx] = rm;
                g_prs[idx] = rs;
            }
        }

    // ---- fused col partials (save slice maxima) ----
    int cslice = blockIdx.y * 4 + wm;
#pragma unroll
    for (int n = 0; n < 8; n++)
#pragma unroll
        for (int q = 0; q < 2; q++) {
            float cm = fmaxf(fmaxf(acc[0][n][q], acc[0][n][2 + q]),
                             fmaxf(acc[1][n][q], acc[1][n][2 + q]));
            cm = fmaxf(cm, __shfl_xor_sync(0xFFFFFFFFu, cm, 4));
            cm = fmaxf(cm, __shfl_xor_sync(0xFFFFFFFFu, cm, 8));
            cm = fmaxf(cm, __shfl_xor_sync(0xFFFFFFFFu, cm, 16));
            float cs = __expf(acc[0][n][q] - cm) + __expf(acc[0][n][2 + q] - cm) +
                       __expf(acc[1][n][q] - cm) + __expf(acc[1][n][2 + q] - cm);
            cs += __shfl_xor_sync(0xFFFFFFFFu, cs, 4);
            cs += __shfl_xor_sync(0xFFFFFFFFu, cs, 8);
            cs += __shfl_xor_sync(0xFFFFFFFFu, cs, 16);
            cmP[n][q] = cm;
            if (g == 0) {
                int j = j0 + wn * 64 + n * 8 + tig * 2 + q;
                size_t idx = (size_t)cslice * NB * HW + b * HW + j;
                g_pcm[idx] = cm;
                g_pcs[idx] = cs;
            }
        }

    // ---- store E = exp(2L - rm_slice - cm_slice) as fp16 ----
    __half* Ep = g_E + (size_t)b * HW * HW;
#pragma unroll
    for (int m = 0; m < 2; m++) {
        int row0 = i0 + (wm * 2 + m) * 16 + g;
#pragma unroll
        for (int n = 0; n < 8; n++) {
            int col = j0 + (wn * 8 + n) * 8 + tig * 2;
            float e0 = __expf(2.0f * acc[m][n][0] - rmP[m][0] - cmP[n][0]);
            float e1 = __expf(2.0f * acc[m][n][1] - rmP[m][0] - cmP[n][1]);
            float e2 = __expf(2.0f * acc[m][n][2] - rmP[m][1] - cmP[n][0]);
            float e3 = __expf(2.0f * acc[m][n][3] - rmP[m][1] - cmP[n][1]);
            *(__half2*)(Ep + (size_t)row0 * HW + col) =
                __floats2half2_rn(e0, e1);
            *(__half2*)(Ep + (size_t)(row0 + 8) * HW + col) =
                __floats2half2_rn(e2, e3);
        }
    }
}

// ---------------------------------------------------------------------------
// Combine kernel: y==0 -> row partials (16), y==1 -> col partials (32)
// ---------------------------------------------------------------------------
__global__ void combine_kernel() {
    int idx = blockIdx.x * 256 + threadIdx.x;
    if (idx >= NB * HW) return;
    if (blockIdx.y == 0) {
        float m = -CUDART_INF_F;
        float mv[NRP], sv[NRP];
#pragma unroll
        for (int p = 0; p < NRP; p++) {
            mv[p] = g_prm[(size_t)p * NB * HW + idx];
            sv[p] = g_prs[(size_t)p * NB * HW + idx];
            m = fmaxf(m, mv[p]);
        }
        float s = 0.0f;
#pragma unroll
        for (int p = 0; p < NRP; p++)
            s += sv[p] * __expf(mv[p] - m);
        g_rmax[idx] = m;
        g_rinv[idx] = 1.0f / s;
    } else {
        float m = -CUDART_INF_F;
        float mv[NCP], sv[NCP];
#pragma unroll
        for (int p = 0; p < NCP; p++) {
            mv[p] = g_pcm[(size_t)p * NB * HW + idx];
            sv[p] = g_pcs[(size_t)p * NB * HW + idx];
            m = fmaxf(m, mv[p]);
        }
        float s = 0.0f;
#pragma unroll
        for (int p = 0; p < NCP; p++)
            s += sv[p] * __expf(mv[p] - m);
        g_cmax[idx] = m;
        g_cinv[idx] = 1.0f / s;
    }
}

// ---------------------------------------------------------------------------
// out[b][perm(j')][i] = E[i][j'] * rowfac[i] * colfac[j']
// rowfac[i] = exp(prm[j0>>6][i] - rmax[i]) * rinv[i]
// colfac[j] = exp(pcm[i0>>5][j] - cmax[j]) * cinv[j]
// ---------------------------------------------------------------------------
__global__ void out_kernel(float* __restrict__ out) {
    __shared__ float sE[32][33];
    __shared__ float rowf[32], colf[32];
    int b  = blockIdx.z;
    int i0 = blockIdx.y * 32;
    int j0 = blockIdx.x * 32;
    int t  = threadIdx.x;

    const __half* Ep = g_E + (size_t)b * HW * HW;
    {
        int row = t >> 3, c4 = (t & 7) * 4;
        const __half* p = Ep + (size_t)(i0 + row) * HW + j0 + c4;
        float2 f01 = __half22float2(*(const __half2*)(p));
        float2 f23 = __half22float2(*(const __half2*)(p + 2));
        sE[row][c4 + 0] = f01.x; sE[row][c4 + 1] = f01.y;
        sE[row][c4 + 2] = f23.x; sE[row][c4 + 3] = f23.y;
    }
    if (t < 32) {
        int i = i0 + t;
        rowf[t] = __expf(g_prm[(size_t)(j0 >> 6) * NB * HW + b * HW + i] -
                         g_rmax[b * HW + i]) * g_rinv[b * HW + i];
    } else if (t < 64) {
        int l = t - 32;
        int j = j0 + l;
        colf[l] = __expf(g_pcm[(size_t)(i0 >> 5) * NB * HW + b * HW + j] -
                         g_cmax[b * HW + j]) * g_cinv[b * HW + j];
    }
    __syncthreads();

    int jrow = t >> 3;
    int ib   = (t & 7) * 4;
    int jn   = j0 + jrow;
    float cf = colf[jrow];
    float4 o;
    o.x = sE[ib + 0][jrow] * rowf[ib + 0] * cf;
    o.y = sE[ib + 1][jrow] * rowf[ib + 1] * cf;
    o.z = sE[ib + 2][jrow] * rowf[ib + 2] * cf;
    o.w = sE[ib + 3][jrow] * rowf[ib + 3] * cf;
    int j = ((jn & 31) << 5) | (jn >> 5);
    *(float4*)(out + ((size_t)b * HW + j) * HW + i0 + ib) = o;
}

// ---------------------------------------------------------------------------
extern "C" void kernel_launch(void* const* d_in, const int* in_sizes, int n_in,
                              void* d_out, int out_size) {
    const float* A  = (const float*)d_in[0];  // feature_A [32,256,32,32]
    const float* Bf = (const float*)d_in[1];  // feature_B [32,256,32,32]
    float* out = (float*)d_out;               // [32,1024,32,32]

    static int smem_set = 0;
    if (!smem_set) {
        cudaFuncSetAttribute(gemm_hmma_kernel,
                             cudaFuncAttributeMaxDynamicSharedMemorySize,
                             GEMM_SMEM);
        smem_set = 1;
    }

    split_frag_kernel<<<dim3(32, 8, 2 * NB), 256>>>(A, Bf);
    gemm_hmma_kernel<<<dim3(8, 8, NB), 256, GEMM_SMEM>>>();
    combine_kernel<<<dim3((NB * HW + 255) / 256, 2), 256>>>();
    out_kernel<<<dim3(32, 32, NB), 256>>>(out);
}

// round 11
// speedup vs baseline: 1.3294x; 1.3294x over previous
#include <cuda_runtime.h>
#include <cuda_fp16.h>
#include <math_constants.h>
#include <cstdint>

#define NB 32
#define NC 256
#define HW 1024
#define NRP 16          // row-partial slices
#define NCP 32          // col-partial slices

static __device__ __constant__ float c_invT = 14.2857142857142857f; // 1/0.07

// fp16 fragment-ordered operands (h/l split, 3-term):
// g_Mp (GEMM-A = feature_B): [b][it16 64][vkt 32][lane 32][4] u32 (fp16x2)
//      vkt<16 = h(kt16), vkt>=16 = l(kt16)
// g_Np (GEMM-B = feature_A*invT): [b][jt8 128][vkt 32][lane 32][2] u32
//      vkt<16 = l(kt16), vkt>=16 = h(kt16)
__device__ uint32_t g_Mp[(size_t)NB * 64 * 32 * 128];
__device__ uint32_t g_Np[(size_t)NB * 128 * 32 * 64];
__device__ __half   g_E[(size_t)NB * HW * HW];   // exp(2L - rm_slice - cm_slice)
__device__ float g_rmax[NB * HW];
__device__ float g_rinv[NB * HW];
__device__ float g_cmax[NB * HW];
__device__ float g_cinv[NB * HW];
__device__ float g_prm[(size_t)NRP * NB * HW];
__device__ float g_prs[(size_t)NRP * NB * HW];
__device__ float g_pcm[(size_t)NCP * NB * HW];
__device__ float g_pcs[(size_t)NCP * NB * HW];

// ---- helpers --------------------------------------------------------------
__device__ __forceinline__ uint32_t h2pack(float x, float y) {
    __half2 h = __floats2half2_rn(x, y);
    return *reinterpret_cast<uint32_t*>(&h);
}
__device__ __forceinline__ uint32_t smem_u32(const void* p) {
    uint32_t a;
    asm("{ .reg .u64 t; cvta.to.shared.u64 t, %1; cvt.u32.u64 %0, t; }"
        : "=r"(a) : "l"(p));
    return a;
}
__device__ __forceinline__ void cp16(uint32_t sdst, const void* gsrc) {
    asm volatile("cp.async.cg.shared.global [%0], [%1], 16;"
                 :: "r"(sdst), "l"(gsrc) : "memory");
}
__device__ __forceinline__ void cp_commit() {
    asm volatile("cp.async.commit_group;" ::: "memory");
}
template <int N>
__device__ __forceinline__ void cp_wait() {
    asm volatile("cp.async.wait_group %0;" :: "n"(N) : "memory");
}
__device__ __forceinline__ void mma_f16(float c[4], const uint32_t a[4],
                                        const uint32_t b[2]) {
    asm volatile(
        "mma.sync.aligned.m16n8k16.row.col.f32.f16.f16.f32 "
        "{%0,%1,%2,%3}, {%4,%5,%6,%7}, {%8,%9}, {%0,%1,%2,%3};"
        : "+f"(c[0]), "+f"(c[1]), "+f"(c[2]), "+f"(c[3])
        : "r"(a[0]), "r"(a[1]), "r"(a[2]), "r"(a[3]), "r"(b[0]), "r"(b[1]));
}

// ---------------------------------------------------------------------------
// Kernel 1: fp16 h/l split + repack into HMMA fragment order.
// grid: (hw/32, c/32, 2*NB), block 256.
// ---------------------------------------------------------------------------
__global__ void split_frag_kernel(const float* __restrict__ A,
                                  const float* __restrict__ Bf) {
    __shared__ float s[32][33];
    int zb   = blockIdx.z;
    int side = zb >> 5;
    int b    = zb & 31;
    int c0   = blockIdx.y * 32;
    int hw0  = blockIdx.x * 32;
    const float* src = (side ? A : Bf) + (size_t)b * NC * HW;
    int t    = threadIdx.x;
    int lane = t & 31;
    int g    = lane >> 2;
    int tig  = lane & 3;
    int blk  = t >> 5;
    {
#pragma unroll
        for (int r = 0; r < 4; r++) {
            int cr = blk + r * 8;
            s[cr][lane] = src[(size_t)(c0 + cr) * HW + hw0 + lane];
        }
    }
    __syncthreads();

    if (side == 0) {
        // A-side: 8 units (it_l 2 x kt16_l 2 x h 2)
        int u = blk >> 1, h = blk & 1;
        int it_l = u >> 1, kt16_l = u & 1;
        uint32_t pk[4];
#pragma unroll
        for (int r = 0; r < 4; r++) {
            int row = it_l * 16 + g + 8 * (r & 1);
            int kb  = kt16_l * 16 + 2 * tig + 8 * (r >> 1);
            float v0 = s[kb][row], v1 = s[kb + 1][row];
            float h0 = __half2float(__float2half_rn(v0));
            float h1 = __half2float(__float2half_rn(v1));
            pk[r] = h ? h2pack(v0 - h0, v1 - h1) : h2pack(h0, h1);
        }
        int it_g = (hw0 >> 4) + it_l;
        int vkt  = h * 16 + (c0 >> 4) + kt16_l;      // h at vkt<16, l at >=16
        size_t o = (((size_t)b * 64 + it_g) * 32 + vkt) * 128 + lane * 4;
        *(uint4*)(g_Mp + o) = make_uint4(pk[0], pk[1], pk[2], pk[3]);
    } else {
        // B-side: 8 units (jt_l 4 x kt16_l 2); write both h and l
        int jt_l = blk & 3, kt16_l = blk >> 2;
        uint32_t ph[2], pl[2];
#pragma unroll
        for (int r = 0; r < 2; r++) {
            int row = jt_l * 8 + g;
            int kb  = kt16_l * 16 + 2 * tig + 8 * r;
            float v0 = s[kb][row] * c_invT, v1 = s[kb + 1][row] * c_invT;
            float h0 = __half2float(__float2half_rn(v0));
            float h1 = __half2float(__float2half_rn(v1));
            ph[r] = h2pack(h0, h1);
            pl[r] = h2pack(v0 - h0, v1 - h1);
        }
        int jt_g = (hw0 >> 3) + jt_l;
        int ckt  = (c0 >> 4) + kt16_l;
        size_t base = ((size_t)b * 128 + jt_g) * 32;
        // l at vkt<16, h at vkt>=16
        *(uint2*)(g_Np + (base + ckt) * 64 + lane * 2)      = make_uint2(pl[0], pl[1]);
        *(uint2*)(g_Np + (base + 16 + ckt) * 64 + lane * 2) = make_uint2(ph[0], ph[1]);
    }
}

// ---------------------------------------------------------------------------
// Kernel 2: fp16 3-term GEMM (h.h + h.l + l.h), 4-stage pipeline,
// fused partial softmax stats + fp16 E out (shared exps).
// Stage (u32 words): [0,1024) Ah | [1024,2048) Al | [2048,3072) Bl | [3072,4096) Bh
// ---------------------------------------------------------------------------
#define STG_U 4096                  // u32 words per stage
#define STG_B (STG_U * 4)           // 16384 bytes
#define GEMM_SMEM (4 * STG_B)       // 65536 bytes

__device__ __forceinline__ void copy_chunk(uint32_t sbase, int ck,
                                           const uint32_t* Mp, const uint32_t* Np,
                                           int t) {
#pragma unroll
    for (int q = 0; q < 2; q++) {   // A: 512 quads (h then l)
        int f4 = t + q * 256;
        int half = f4 >> 8, it = (f4 >> 5) & 7, rem = f4 & 31;
        cp16(sbase + (uint32_t)(half * 1024 + it * 128 + rem * 4) * 4,
             Mp + ((size_t)it * 32 + ck + half * 16) * 128 + rem * 4);
    }
#pragma unroll
    for (int q = 0; q < 2; q++) {   // B: 512 quads (l then h)
        int f4 = t + q * 256;
        int half = f4 >> 8, jt = (f4 >> 4) & 15, rem = f4 & 15;
        cp16(sbase + (uint32_t)(2048 + half * 1024 + jt * 64 + rem * 4) * 4,
             Np + ((size_t)jt * 32 + ck + half * 16) * 64 + rem * 4);
    }
    cp_commit();
}

__global__ void __launch_bounds__(256, 2) gemm_hmma_kernel() {
    extern __shared__ uint32_t smu[];
    uint32_t sbase = smem_u32(smu);
    int b   = blockIdx.z;
    int jt0 = blockIdx.x * 16;     // j0 = bx*128
    int it0 = blockIdx.y * 8;      // i0 = by*128
    int t    = threadIdx.x;
    int wid  = t >> 5;
    int lane = t & 31;
    int wm   = wid >> 1;
    int wn   = wid & 1;
    int g    = lane >> 2;
    int tig  = lane & 3;

    const uint32_t* Mp = g_Mp + ((size_t)b * 64 + it0) * 4096;
    const uint32_t* Np = g_Np + ((size_t)b * 128 + jt0) * 2048;

    float acc[2][8][4];
#pragma unroll
    for (int m = 0; m < 2; m++)
#pragma unroll
        for (int n = 0; n < 8; n++)
#pragma unroll
            for (int r = 0; r < 4; r++) acc[m][n][r] = 0.0f;

    copy_chunk(sbase + 0 * STG_B, 0, Mp, Np, t);
    copy_chunk(sbase + 1 * STG_B, 1, Mp, Np, t);
    copy_chunk(sbase + 2 * STG_B, 2, Mp, Np, t);

    for (int c = 0; c < 16; c++) {
        if (c <= 13) cp_wait<2>();
        else if (c == 14) cp_wait<1>();
        else cp_wait<0>();
        __syncthreads();
        if (c + 3 < 16)
            copy_chunk(sbase + ((c + 3) & 3) * STG_B, c + 3, Mp, Np, t);

        const uint32_t* S = smu + (c & 3) * STG_U;
        uint32_t ah[2][4], al[2][4];
#pragma unroll
        for (int m = 0; m < 2; m++) {
            uint4 vh = *(const uint4*)(S + (wm * 2 + m) * 128 + lane * 4);
            uint4 vl = *(const uint4*)(S + 1024 + (wm * 2 + m) * 128 + lane * 4);
            ah[m][0] = vh.x; ah[m][1] = vh.y; ah[m][2] = vh.z; ah[m][3] = vh.w;
            al[m][0] = vl.x; al[m][1] = vl.y; al[m][2] = vl.z; al[m][3] = vl.w;
        }
#pragma unroll
        for (int ng = 0; ng < 2; ng++) {
            uint32_t bh[4][2], bl[4][2];
#pragma unroll
            for (int n = 0; n < 4; n++) {
                int jt = wn * 8 + ng * 4 + n;
                uint2 vl = *(const uint2*)(S + 2048 + jt * 64 + lane * 2);
                uint2 vh = *(const uint2*)(S + 3072 + jt * 64 + lane * 2);
                bl[n][0] = vl.x; bl[n][1] = vl.y;
                bh[n][0] = vh.x; bh[n][1] = vh.y;
            }
#pragma unroll
            for (int m = 0; m < 2; m++)
#pragma unroll
                for (int n = 0; n < 4; n++) {
                    float* a = acc[m][ng * 4 + n];
                    mma_f16(a, ah[m], bh[n]);
                    mma_f16(a, ah[m], bl[n]);
                    mma_f16(a, al[m], bh[n]);
                }
        }
    }

    int j0 = jt0 * 8;
    int i0 = it0 * 16;

    // ---- slice maxima ----
    float rmP[2][2];
#pragma unroll
    for (int m = 0; m < 2; m++)
#pragma unroll
        for (int rp = 0; rp < 2; rp++) {
            float rm = -CUDART_INF_F;
#pragma unroll
            for (int n = 0; n < 8; n++)
                rm = fmaxf(rm, fmaxf(acc[m][n][rp * 2], acc[m][n][rp * 2 + 1]));
            rm = fmaxf(rm, __shfl_xor_sync(0xFFFFFFFFu, rm, 1));
            rm = fmaxf(rm, __shfl_xor_sync(0xFFFFFFFFu, rm, 2));
            rmP[m][rp] = rm;
        }
    float cmP[8][2];
#pragma unroll
    for (int n = 0; n < 8; n++)
#pragma unroll
        for (int q = 0; q < 2; q++) {
            float cm = fmaxf(fmaxf(acc[0][n][q], acc[0][n][2 + q]),
                             fmaxf(acc[1][n][q], acc[1][n][2 + q]));
            cm = fmaxf(cm, __shfl_xor_sync(0xFFFFFFFFu, cm, 4));
            cm = fmaxf(cm, __shfl_xor_sync(0xFFFFFFFFu, cm, 8));
            cm = fmaxf(cm, __shfl_xor_sync(0xFFFFFFFFu, cm, 16));
            cmP[n][q] = cm;
        }

    // ---- single exp pass: stats sums + E store (E = e_r * e_c) ----
    float rs[2][2] = {{0.f, 0.f}, {0.f, 0.f}};
    float cs[8][2];
#pragma unroll
    for (int n = 0; n < 8; n++) { cs[n][0] = 0.f; cs[n][1] = 0.f; }

    __half* Ep = g_E + (size_t)b * HW * HW;
#pragma unroll
    for (int m = 0; m < 2; m++) {
        int row0 = i0 + (wm * 2 + m) * 16 + g;
#pragma unroll
        for (int n = 0; n < 8; n++) {
            int col = j0 + (wn * 8 + n) * 8 + tig * 2;
            float er0 = __expf(acc[m][n][0] - rmP[m][0]);
            float er1 = __expf(acc[m][n][1] - rmP[m][0]);
            float er2 = __expf(acc[m][n][2] - rmP[m][1]);
            float er3 = __expf(acc[m][n][3] - rmP[m][1]);
            float ec0 = __expf(acc[m][n][0] - cmP[n][0]);
            float ec1 = __expf(acc[m][n][1] - cmP[n][1]);
            float ec2 = __expf(acc[m][n][2] - cmP[n][0]);
            float ec3 = __expf(acc[m][n][3] - cmP[n][1]);
            rs[m][0] += er0 + er1;
            rs[m][1] += er2 + er3;
            cs[n][0] += ec0 + ec2;
            cs[n][1] += ec1 + ec3;
            *(__half2*)(Ep + (size_t)row0 * HW + col) =
                __floats2half2_rn(er0 * ec0, er1 * ec1);
            *(__half2*)(Ep + (size_t)(row0 + 8) * HW + col) =
                __floats2half2_rn(er2 * ec2, er3 * ec3);
        }
    }

    // ---- reduce + write row partials ----
    int rslice = blockIdx.x * 2 + wn;
#pragma unroll
    for (int m = 0; m < 2; m++)
#pragma unroll
        for (int rp = 0; rp < 2; rp++) {
            float v = rs[m][rp];
            v += __shfl_xor_sync(0xFFFFFFFFu, v, 1);
            v += __shfl_xor_sync(0xFFFFFFFFu, v, 2);
            if (tig == 0) {
                int i = i0 + wm * 32 + m * 16 + rp * 8 + g;
                size_t idx = (size_t)rslice * NB * HW + b * HW + i;
                g_prm[idx] = rmP[m][rp];
                g_prs[idx] = v;
            }
        }

    // ---- reduce + write col partials ----
    int cslice = blockIdx.y * 4 + wm;
#pragma unroll
    for (int n = 0; n < 8; n++)
#pragma unroll
        for (int q = 0; q < 2; q++) {
            float v = cs[n][q];
            v += __shfl_xor_sync(0xFFFFFFFFu, v, 4);
            v += __shfl_xor_sync(0xFFFFFFFFu, v, 8);
            v += __shfl_xor_sync(0xFFFFFFFFu, v, 16);
            if (g == 0) {
                int j = j0 + wn * 64 + n * 8 + tig * 2 + q;
                size_t idx = (size_t)cslice * NB * HW + b * HW + j;
                g_pcm[idx] = cmP[n][q];
                g_pcs[idx] = v;
            }
        }
}

// ---------------------------------------------------------------------------
// Combine kernel: y==0 -> row partials (16), y==1 -> col partials (32)
// ---------------------------------------------------------------------------
__global__ void combine_kernel() {
    int idx = blockIdx.x * 256 + threadIdx.x;
    if (idx >= NB * HW) return;
    if (blockIdx.y == 0) {
        float m = -CUDART_INF_F;
        float mv[NRP], sv[NRP];
#pragma unroll
        for (int p = 0; p < NRP; p++) {
            mv[p] = g_prm[(size_t)p * NB * HW + idx];
            sv[p] = g_prs[(size_t)p * NB * HW + idx];
            m = fmaxf(m, mv[p]);
        }
        float s = 0.0f;
#pragma unroll
        for (int p = 0; p < NRP; p++)
            s += sv[p] * __expf(mv[p] - m);
        g_rmax[idx] = m;
        g_rinv[idx] = 1.0f / s;
    } else {
        float m = -CUDART_INF_F;
        float mv[NCP], sv[NCP];
#pragma unroll
        for (int p = 0; p < NCP; p++) {
            mv[p] = g_pcm[(size_t)p * NB * HW + idx];
            sv[p] = g_pcs[(size_t)p * NB * HW + idx];
            m = fmaxf(m, mv[p]);
        }
        float s = 0.0f;
#pragma unroll
        for (int p = 0; p < NCP; p++)
            s += sv[p] * __expf(mv[p] - m);
        g_cmax[idx] = m;
        g_cinv[idx] = 1.0f / s;
    }
}

// ---------------------------------------------------------------------------
// out[b][perm(j')][i] = E[i][j'] * rowfac[i] * colfac[j']
// rowfac[i] = exp(prm[j0>>6][i] - rmax[i]) * rinv[i]
// colfac[j] = exp(pcm[i0>>5][j] - cmax[j]) * cinv[j]
// ---------------------------------------------------------------------------
__global__ void out_kernel(float* __restrict__ out) {
    __shared__ float sE[32][33];
    __shared__ float rowf[32], colf[32];
    int b  = blockIdx.z;
    int i0 = blockIdx.y * 32;
    int j0 = blockIdx.x * 32;
    int t  = threadIdx.x;

    const __half* Ep = g_E + (size_t)b * HW * HW;
    {
        int row = t >> 3, c4 = (t & 7) * 4;
        const __half* p = Ep + (size_t)(i0 + row) * HW + j0 + c4;
        float2 f01 = __half22float2(*(const __half2*)(p));
        float2 f23 = __half22float2(*(const __half2*)(p + 2));
        sE[row][c4 + 0] = f01.x; sE[row][c4 + 1] = f01.y;
        sE[row][c4 + 2] = f23.x; sE[row][c4 + 3] = f23.y;
    }
    if (t < 32) {
        int i = i0 + t;
        rowf[t] = __expf(g_prm[(size_t)(j0 >> 6) * NB * HW + b * HW + i] -
                         g_rmax[b * HW + i]) * g_rinv[b * HW + i];
    } else if (t < 64) {
        int l = t - 32;
        int j = j0 + l;
        colf[l] = __expf(g_pcm[(size_t)(i0 >> 5) * NB * HW + b * HW + j] -
                         g_cmax[b * HW + j]) * g_cinv[b * HW + j];
    }
    __syncthreads();

    int jrow = t >> 3;
    int ib   = (t & 7) * 4;
    int jn   = j0 + jrow;
    float cf = colf[jrow];
    float4 o;
    o.x = sE[ib + 0][jrow] * rowf[ib + 0] * cf;
    o.y = sE[ib + 1][jrow] * rowf[ib + 1] * cf;
    o.z = sE[ib + 2][jrow] * rowf[ib + 2] * cf;
    o.w = sE[ib + 3][jrow] * rowf[ib + 3] * cf;
    int j = ((jn & 31) << 5) | (jn >> 5);
    *(float4*)(out + ((size_t)b * HW + j) * HW + i0 + ib) = o;
}

// ---------------------------------------------------------------------------
extern "C" void kernel_launch(void* const* d_in, const int* in_sizes, int n_in,
                              void* d_out, int out_size) {
    const float* A  = (const float*)d_in[0];  // feature_A [32,256,32,32]
    const float* Bf = (const float*)d_in[1];  // feature_B [32,256,32,32]
    float* out = (float*)d_out;               // [32,1024,32,32]

    static int smem_set = 0;
    if (!smem_set) {
        cudaFuncSetAttribute(gemm_hmma_kernel,
                             cudaFuncAttributeMaxDynamicSharedMemorySize,
                             GEMM_SMEM);
        smem_set = 1;
    }

    split_frag_kernel<<<dim3(32, 8, 2 * NB), 256>>>(A, Bf);
    gemm_hmma_kernel<<<dim3(8, 8, NB), 256, GEMM_SMEM>>>();
    combine_kernel<<<dim3((NB * HW + 255) / 256, 2), 256>>>();
    out_kernel<<<dim3(32, 32, NB), 256>>>(out);
}

// round 12
// speedup vs baseline: 1.4663x; 1.1030x over previous
#include <cuda_runtime.h>
#include <cuda_fp16.h>
#include <math_constants.h>
#include <cstdint>

#define NB 32
#define NC 256
#define HW 1024
#define NRP 16          // row-partial slices
#define NCP 32          // col-partial slices

static __device__ __constant__ float c_invT = 14.2857142857142857f; // 1/0.07

// fp16 fragment-ordered operands (h/l split, 3-term):
// g_Mp (GEMM-A = feature_B): [b][it16 64][vkt 32][lane 32][4] u32 (fp16x2)
// g_Np (GEMM-B = feature_A*invT): [b][jt8 128][vkt 32][lane 32][2] u32
__device__ uint32_t g_Mp[(size_t)NB * 64 * 32 * 128];
__device__ uint32_t g_Np[(size_t)NB * 128 * 32 * 64];
__device__ __half   g_E[(size_t)NB * HW * HW];   // exp(2L - rm_slice - cm_slice)
// NOTE: all *max/partial-max values below live in the log2 domain.
__device__ float g_rmax[NB * HW];
__device__ float g_rinv[NB * HW];
__device__ float g_cmax[NB * HW];
__device__ float g_cinv[NB * HW];
__device__ float g_prm[(size_t)NRP * NB * HW];
__device__ float g_prs[(size_t)NRP * NB * HW];
__device__ float g_pcm[(size_t)NCP * NB * HW];
__device__ float g_pcs[(size_t)NCP * NB * HW];

// ---- helpers --------------------------------------------------------------
__device__ __forceinline__ float ex2(float x) {
    float r;
    asm("ex2.approx.ftz.f32 %0, %1;" : "=f"(r) : "f"(x));
    return r;
}
__device__ __forceinline__ uint32_t h2pack(float x, float y) {
    __half2 h = __floats2half2_rn(x, y);
    return *reinterpret_cast<uint32_t*>(&h);
}
__device__ __forceinline__ uint32_t smem_u32(const void* p) {
    uint32_t a;
    asm("{ .reg .u64 t; cvta.to.shared.u64 t, %1; cvt.u32.u64 %0, t; }"
        : "=r"(a) : "l"(p));
    return a;
}
__device__ __forceinline__ void cp16(uint32_t sdst, const void* gsrc) {
    asm volatile("cp.async.cg.shared.global [%0], [%1], 16;"
                 :: "r"(sdst), "l"(gsrc) : "memory");
}
__device__ __forceinline__ void cp_commit() {
    asm volatile("cp.async.commit_group;" ::: "memory");
}
template <int N>
__device__ __forceinline__ void cp_wait() {
    asm volatile("cp.async.wait_group %0;" :: "n"(N) : "memory");
}
__device__ __forceinline__ void mma_f16(float c[4], const uint32_t a[4],
                                        const uint32_t b[2]) {
    asm volatile(
        "mma.sync.aligned.m16n8k16.row.col.f32.f16.f16.f32 "
        "{%0,%1,%2,%3}, {%4,%5,%6,%7}, {%8,%9}, {%0,%1,%2,%3};"
        : "+f"(c[0]), "+f"(c[1]), "+f"(c[2]), "+f"(c[3])
        : "r"(a[0]), "r"(a[1]), "r"(a[2]), "r"(a[3]), "r"(b[0]), "r"(b[1]));
}

// ---------------------------------------------------------------------------
// Kernel 1: fp16 h/l split + repack into HMMA fragment order.
// ---------------------------------------------------------------------------
__global__ void split_frag_kernel(const float* __restrict__ A,
                                  const float* __restrict__ Bf) {
    __shared__ float s[32][33];
    int zb   = blockIdx.z;
    int side = zb >> 5;
    int b    = zb & 31;
    int c0   = blockIdx.y * 32;
    int hw0  = blockIdx.x * 32;
    const float* src = (side ? A : Bf) + (size_t)b * NC * HW;
    int t    = threadIdx.x;
    int lane = t & 31;
    int g    = lane >> 2;
    int tig  = lane & 3;
    int blk  = t >> 5;
    {
#pragma unroll
        for (int r = 0; r < 4; r++) {
            int cr = blk + r * 8;
            s[cr][lane] = src[(size_t)(c0 + cr) * HW + hw0 + lane];
        }
    }
    __syncthreads();

    if (side == 0) {
        int u = blk >> 1, h = blk & 1;
        int it_l = u >> 1, kt16_l = u & 1;
        uint32_t pk[4];
#pragma unroll
        for (int r = 0; r < 4; r++) {
            int row = it_l * 16 + g + 8 * (r & 1);
            int kb  = kt16_l * 16 + 2 * tig + 8 * (r >> 1);
            float v0 = s[kb][row], v1 = s[kb + 1][row];
            float h0 = __half2float(__float2half_rn(v0));
            float h1 = __half2float(__float2half_rn(v1));
            pk[r] = h ? h2pack(v0 - h0, v1 - h1) : h2pack(h0, h1);
        }
        int it_g = (hw0 >> 4) + it_l;
        int vkt  = h * 16 + (c0 >> 4) + kt16_l;
        size_t o = (((size_t)b * 64 + it_g) * 32 + vkt) * 128 + lane * 4;
        *(uint4*)(g_Mp + o) = make_uint4(pk[0], pk[1], pk[2], pk[3]);
    } else {
        int jt_l = blk & 3, kt16_l = blk >> 2;
        uint32_t ph[2], pl[2];
#pragma unroll
        for (int r = 0; r < 2; r++) {
            int row = jt_l * 8 + g;
            int kb  = kt16_l * 16 + 2 * tig + 8 * r;
            float v0 = s[kb][row] * c_invT, v1 = s[kb + 1][row] * c_invT;
            float h0 = __half2float(__float2half_rn(v0));
            float h1 = __half2float(__float2half_rn(v1));
            ph[r] = h2pack(h0, h1);
            pl[r] = h2pack(v0 - h0, v1 - h1);
        }
        int jt_g = (hw0 >> 3) + jt_l;
        int ckt  = (c0 >> 4) + kt16_l;
        size_t base = ((size_t)b * 128 + jt_g) * 32;
        *(uint2*)(g_Np + (base + ckt) * 64 + lane * 2)      = make_uint2(pl[0], pl[1]);
        *(uint2*)(g_Np + (base + 16 + ckt) * 64 + lane * 2) = make_uint2(ph[0], ph[1]);
    }
}

// ---------------------------------------------------------------------------
// Kernel 2: fp16 3-term GEMM, 4-stage pipeline, fused stats (log2 domain)
// + fp16 E out.
// Stage (u32 words): [0,1024) Ah | [1024,2048) Al | [2048,3072) Bl | [3072,4096) Bh
// ---------------------------------------------------------------------------
#define STG_U 4096
#define STG_B (STG_U * 4)
#define GEMM_SMEM (4 * STG_B)       // 65536 bytes

__device__ __forceinline__ void copy_chunk(uint32_t sbase, int ck,
                                           const uint32_t* Mp, const uint32_t* Np,
                                           int t) {
#pragma unroll
    for (int q = 0; q < 2; q++) {
        int f4 = t + q * 256;
        int half = f4 >> 8, it = (f4 >> 5) & 7, rem = f4 & 31;
        cp16(sbase + (uint32_t)(half * 1024 + it * 128 + rem * 4) * 4,
             Mp + ((size_t)it * 32 + ck + half * 16) * 128 + rem * 4);
    }
#pragma unroll
    for (int q = 0; q < 2; q++) {
        int f4 = t + q * 256;
        int half = f4 >> 8, jt = (f4 >> 4) & 15, rem = f4 & 15;
        cp16(sbase + (uint32_t)(2048 + half * 1024 + jt * 64 + rem * 4) * 4,
             Np + ((size_t)jt * 32 + ck + half * 16) * 64 + rem * 4);
    }
    cp_commit();
}

__global__ void __launch_bounds__(256, 2) gemm_hmma_kernel() {
    extern __shared__ uint32_t smu[];
    uint32_t sbase = smem_u32(smu);
    int b   = blockIdx.z;
    int jt0 = blockIdx.x * 16;     // j0 = bx*128
    int it0 = blockIdx.y * 8;      // i0 = by*128
    int t    = threadIdx.x;
    int wid  = t >> 5;
    int lane = t & 31;
    int wm   = wid >> 1;
    int wn   = wid & 1;
    int g    = lane >> 2;
    int tig  = lane & 3;

    const uint32_t* Mp = g_Mp + ((size_t)b * 64 + it0) * 4096;
    const uint32_t* Np = g_Np + ((size_t)b * 128 + jt0) * 2048;

    float acc[2][8][4];
#pragma unroll
    for (int m = 0; m < 2; m++)
#pragma unroll
        for (int n = 0; n < 8; n++)
#pragma unroll
            for (int r = 0; r < 4; r++) acc[m][n][r] = 0.0f;

    copy_chunk(sbase + 0 * STG_B, 0, Mp, Np, t);
    copy_chunk(sbase + 1 * STG_B, 1, Mp, Np, t);
    copy_chunk(sbase + 2 * STG_B, 2, Mp, Np, t);

    for (int c = 0; c < 16; c++) {
        if (c <= 13) cp_wait<2>();
        else if (c == 14) cp_wait<1>();
        else cp_wait<0>();
        __syncthreads();
        if (c + 3 < 16)
            copy_chunk(sbase + ((c + 3) & 3) * STG_B, c + 3, Mp, Np, t);

        const uint32_t* S = smu + (c & 3) * STG_U;
        uint32_t ah[2][4], al[2][4];
#pragma unroll
        for (int m = 0; m < 2; m++) {
            uint4 vh = *(const uint4*)(S + (wm * 2 + m) * 128 + lane * 4);
            uint4 vl = *(const uint4*)(S + 1024 + (wm * 2 + m) * 128 + lane * 4);
            ah[m][0] = vh.x; ah[m][1] = vh.y; ah[m][2] = vh.z; ah[m][3] = vh.w;
            al[m][0] = vl.x; al[m][1] = vl.y; al[m][2] = vl.z; al[m][3] = vl.w;
        }
#pragma unroll
        for (int ng = 0; ng < 2; ng++) {
            uint32_t bh[4][2], bl[4][2];
#pragma unroll
            for (int n = 0; n < 4; n++) {
                int jt = wn * 8 + ng * 4 + n;
                uint2 vl = *(const uint2*)(S + 2048 + jt * 64 + lane * 2);
                uint2 vh = *(const uint2*)(S + 3072 + jt * 64 + lane * 2);
                bl[n][0] = vl.x; bl[n][1] = vl.y;
                bh[n][0] = vh.x; bh[n][1] = vh.y;
            }
#pragma unroll
            for (int m = 0; m < 2; m++)
#pragma unroll
                for (int n = 0; n < 4; n++) {
                    float* a = acc[m][ng * 4 + n];
                    mma_f16(a, ah[m], bh[n]);
                    mma_f16(a, ah[m], bl[n]);
                    mma_f16(a, al[m], bh[n]);
                }
        }
    }

    // ---- move to log2 domain once ----
    const float L2E = 1.44269504088896f;
#pragma unroll
    for (int m = 0; m < 2; m++)
#pragma unroll
        for (int n = 0; n < 8; n++)
#pragma unroll
            for (int r = 0; r < 4; r++) acc[m][n][r] *= L2E;

    int j0 = jt0 * 8;
    int i0 = it0 * 16;

    // ---- slice maxima (log2 domain) ----
    float rmP[2][2];
#pragma unroll
    for (int m = 0; m < 2; m++)
#pragma unroll
        for (int rp = 0; rp < 2; rp++) {
            float rm = -CUDART_INF_F;
#pragma unroll
            for (int n = 0; n < 8; n++)
                rm = fmaxf(rm, fmaxf(acc[m][n][rp * 2], acc[m][n][rp * 2 + 1]));
            rm = fmaxf(rm, __shfl_xor_sync(0xFFFFFFFFu, rm, 1));
            rm = fmaxf(rm, __shfl_xor_sync(0xFFFFFFFFu, rm, 2));
            rmP[m][rp] = rm;
        }
    float cmP[8][2];
#pragma unroll
    for (int n = 0; n < 8; n++)
#pragma unroll
        for (int q = 0; q < 2; q++) {
            float cm = fmaxf(fmaxf(acc[0][n][q], acc[0][n][2 + q]),
                             fmaxf(acc[1][n][q], acc[1][n][2 + q]));
            cm = fmaxf(cm, __shfl_xor_sync(0xFFFFFFFFu, cm, 4));
            cm = fmaxf(cm, __shfl_xor_sync(0xFFFFFFFFu, cm, 8));
            cm = fmaxf(cm, __shfl_xor_sync(0xFFFFFFFFu, cm, 16));
            cmP[n][q] = cm;
        }

    // ---- single exp pass: stats sums + E store (E = e_r * e_c) ----
    float rs[2][2] = {{0.f, 0.f}, {0.f, 0.f}};
    float cs[8][2];
#pragma unroll
    for (int n = 0; n < 8; n++) { cs[n][0] = 0.f; cs[n][1] = 0.f; }

    __half* Ep = g_E + (size_t)b * HW * HW;
#pragma unroll
    for (int m = 0; m < 2; m++) {
        int row0 = i0 + (wm * 2 + m) * 16 + g;
#pragma unroll
        for (int n = 0; n < 8; n++) {
            int col = j0 + (wn * 8 + n) * 8 + tig * 2;
            float er0 = ex2(acc[m][n][0] - rmP[m][0]);
            float er1 = ex2(acc[m][n][1] - rmP[m][0]);
            float er2 = ex2(acc[m][n][2] - rmP[m][1]);
            float er3 = ex2(acc[m][n][3] - rmP[m][1]);
            float ec0 = ex2(acc[m][n][0] - cmP[n][0]);
            float ec1 = ex2(acc[m][n][1] - cmP[n][1]);
            float ec2 = ex2(acc[m][n][2] - cmP[n][0]);
            float ec3 = ex2(acc[m][n][3] - cmP[n][1]);
            rs[m][0] += er0 + er1;
            rs[m][1] += er2 + er3;
            cs[n][0] += ec0 + ec2;
            cs[n][1] += ec1 + ec3;
            *(__half2*)(Ep + (size_t)row0 * HW + col) =
                __floats2half2_rn(er0 * ec0, er1 * ec1);
            *(__half2*)(Ep + (size_t)(row0 + 8) * HW + col) =
                __floats2half2_rn(er2 * ec2, er3 * ec3);
        }
    }

    // ---- reduce + write row partials ----
    int rslice = blockIdx.x * 2 + wn;
#pragma unroll
    for (int m = 0; m < 2; m++)
#pragma unroll
        for (int rp = 0; rp < 2; rp++) {
            float v = rs[m][rp];
            v += __shfl_xor_sync(0xFFFFFFFFu, v, 1);
            v += __shfl_xor_sync(0xFFFFFFFFu, v, 2);
            if (tig == 0) {
                int i = i0 + wm * 32 + m * 16 + rp * 8 + g;
                size_t idx = (size_t)rslice * NB * HW + b * HW + i;
                g_prm[idx] = rmP[m][rp];
                g_prs[idx] = v;
            }
        }

    // ---- reduce + write col partials ----
    int cslice = blockIdx.y * 4 + wm;
#pragma unroll
    for (int n = 0; n < 8; n++)
#pragma unroll
        for (int q = 0; q < 2; q++) {
            float v = cs[n][q];
            v += __shfl_xor_sync(0xFFFFFFFFu, v, 4);
            v += __shfl_xor_sync(0xFFFFFFFFu, v, 8);
            v += __shfl_xor_sync(0xFFFFFFFFu, v, 16);
            if (g == 0) {
                int j = j0 + wn * 64 + n * 8 + tig * 2 + q;
                size_t idx = (size_t)cslice * NB * HW + b * HW + j;
                g_pcm[idx] = cmP[n][q];
                g_pcs[idx] = v;
            }
        }
}

// ---------------------------------------------------------------------------
// Combine kernel (log2 domain): y==0 -> row partials, y==1 -> col partials
// ---------------------------------------------------------------------------
__global__ void combine_kernel() {
    int idx = blockIdx.x * 256 + threadIdx.x;
    if (idx >= NB * HW) return;
    if (blockIdx.y == 0) {
        float m = -CUDART_INF_F;
        float mv[NRP], sv[NRP];
#pragma unroll
        for (int p = 0; p < NRP; p++) {
            mv[p] = g_prm[(size_t)p * NB * HW + idx];
            sv[p] = g_prs[(size_t)p * NB * HW + idx];
            m = fmaxf(m, mv[p]);
        }
        float s = 0.0f;
#pragma unroll
        for (int p = 0; p < NRP; p++)
            s += sv[p] * ex2(mv[p] - m);
        g_rmax[idx] = m;
        g_rinv[idx] = 1.0f / s;
    } else {
        float m = -CUDART_INF_F;
        float mv[NCP], sv[NCP];
#pragma unroll
        for (int p = 0; p < NCP; p++) {
            mv[p] = g_pcm[(size_t)p * NB * HW + idx];
            sv[p] = g_pcs[(size_t)p * NB * HW + idx];
            m = fmaxf(m, mv[p]);
        }
        float s = 0.0f;
#pragma unroll
        for (int p = 0; p < NCP; p++)
            s += sv[p] * ex2(mv[p] - m);
        g_cmax[idx] = m;
        g_cinv[idx] = 1.0f / s;
    }
}

// ---------------------------------------------------------------------------
// out kernel: tile 32 jn x 128 i per block (grid 32 x 8 x NB).
// out[b][perm(jn)][i] = E[i][jn] * rowf[i] * colf[i>>5][jn]
// rowf[i] = 2^(prm[j0>>6][i] - rmax[i]) * rinv[i]
// colf[isl][j] = 2^(pcm[(i0>>5)+isl][j] - cmax[j]) * cinv[j]
// ---------------------------------------------------------------------------
__global__ void out_kernel(float* __restrict__ out) {
    __shared__ float sE[128][33];
    __shared__ float rowf[128];
    __shared__ float colf[4][32];
    int b  = blockIdx.z;
    int i0 = blockIdx.y * 128;
    int j0 = blockIdx.x * 32;
    int t  = threadIdx.x;

    const __half* Ep = g_E + (size_t)b * HW * HW;
#pragma unroll
    for (int q = 0; q < 2; q++) {
        int idx = t + q * 256;          // 0..511
        int row = idx >> 2;             // 0..127
        int c8  = (idx & 3) * 8;        // 0,8,16,24
        uint4 v = *(const uint4*)(Ep + (size_t)(i0 + row) * HW + j0 + c8);
        const __half2* hp = (const __half2*)&v;
#pragma unroll
        for (int e = 0; e < 4; e++) {
            float2 f = __half22float2(hp[e]);
            sE[row][c8 + e * 2]     = f.x;
            sE[row][c8 + e * 2 + 1] = f.y;
        }
    }
    if (t < 128) {
        int i = i0 + t;
        rowf[t] = ex2(g_prm[(size_t)(j0 >> 6) * NB * HW + b * HW + i] -
                      g_rmax[b * HW + i]) * g_rinv[b * HW + i];
    } else {
        int l   = t - 128;
        int isl = l >> 5;
        int jl  = l & 31;
        int j   = j0 + jl;
        int cslice = (i0 >> 5) + isl;
        colf[isl][jl] = ex2(g_pcm[(size_t)cslice * NB * HW + b * HW + j] -
                            g_cmax[b * HW + j]) * g_cinv[b * HW + j];
    }
    __syncthreads();

    int jl  = t >> 3;          // 0..31
    int ic0 = (t & 7) * 4;     // 0..28
    int jn  = j0 + jl;
    int j   = ((jn & 31) << 5) | (jn >> 5);
    float* op = out + ((size_t)b * HW + j) * HW + i0;
#pragma unroll
    for (int q = 0; q < 4; q++) {
        int ib = ic0 + q * 32;      // 0..127
        float cf = colf[ib >> 5][jl];
        float4 o;
        o.x = sE[ib + 0][jl] * rowf[ib + 0] * cf;
        o.y = sE[ib + 1][jl] * rowf[ib + 1] * cf;
        o.z = sE[ib + 2][jl] * rowf[ib + 2] * cf;
        o.w = sE[ib + 3][jl] * rowf[ib + 3] * cf;
        *(float4*)(op + ib) = o;
    }
}

// ---------------------------------------------------------------------------
extern "C" void kernel_launch(void* const* d_in, const int* in_sizes, int n_in,
                              void* d_out, int out_size) {
    const float* A  = (const float*)d_in[0];  // feature_A [32,256,32,32]
    const float* Bf = (const float*)d_in[1];  // feature_B [32,256,32,32]
    float* out = (float*)d_out;               // [32,1024,32,32]

    static int smem_set = 0;
    if (!smem_set) {
        cudaFuncSetAttribute(gemm_hmma_kernel,
                             cudaFuncAttributeMaxDynamicSharedMemorySize,
                             GEMM_SMEM);
        smem_set = 1;
    }

    split_frag_kernel<<<dim3(32, 8, 2 * NB), 256>>>(A, Bf);
    gemm_hmma_kernel<<<dim3(8, 8, NB), 256, GEMM_SMEM>>>();
    combine_kernel<<<dim3((NB * HW + 255) / 256, 2), 256>>>();
    out_kernel<<<dim3(32, 8, NB), 256>>>(out);
}